// round 2
// baseline (speedup 1.0000x reference)
#include <cuda_runtime.h>

#define Bb 32
#define Nn 1024
#define Hh 128
#define ROWS_PER_BLOCK 16
#define THREADS 512

__device__ float g_prm[9];   // u0..2, au, v0..2, av, kd  (pre-scaled by log2 e)
__device__ int   g_mask_byte; // 1 if masks are 1-byte bools, 0 if int32

__device__ __forceinline__ float ex2f_(float x) {
    float y; asm("ex2.approx.ftz.f32 %0, %1;" : "=f"(y) : "f"(x)); return y;
}
__device__ __forceinline__ float rsqrtf_(float x) {
    float y; asm("rsqrt.approx.ftz.f32 %0, %1;" : "=f"(y) : "f"(x)); return y;
}
__device__ __forceinline__ bool mask_at(const void* m, int idx, int isByte) {
    if (isByte) return ((const unsigned char*)m)[idx] != 0;
    return ((const int*)m)[idx] != 0;
}

// ---------------------------------------------------------------------------
// Mask-dtype detector. Reads B*N/4 words = 32KB, safe under both layouts.
// Bool-byte masks produce packed words with high bytes set (>1) w.p. ~1.
// ---------------------------------------------------------------------------
__global__ void detect_kernel(const unsigned int* __restrict__ nm) {
    int any = 0;
    for (int k = threadIdx.x; k < (Bb * Nn) / 4; k += blockDim.x)
        if (nm[k] > 1u) any = 1;
    int r = __syncthreads_or(any);
    if (threadIdx.x == 0) g_mask_byte = r ? 1 : 0;
}

// ---------------------------------------------------------------------------
// Setup: collapse the H dimension into 9 scalars. One warp.
// ---------------------------------------------------------------------------
__global__ void setup_kernel(const float* __restrict__ lin1_w,
                             const float* __restrict__ lin1_b,
                             const float* __restrict__ wp,
                             const float* __restrict__ bp,
                             const float* __restrict__ wd,
                             const float* __restrict__ wc) {
    const float L2E = 1.4426950408889634f;
    int lane = threadIdx.x;
    float u0 = 0.f, u1 = 0.f, u2 = 0.f, au = 0.f;
    float v0 = 0.f, v1 = 0.f, v2 = 0.f, av = 0.f, kd = 0.f;
    for (int h = lane; h < Hh; h += 32) {
        float w1h = wc[h];
        float w2h = wc[Hh + h];
        float a = lin1_w[h] * w1h;
        float c = lin1_b[h] * w1h;
        float wp0 = wp[h * 3 + 0], wp1 = wp[h * 3 + 1], wp2 = wp[h * 3 + 2];
        u0 = fmaf(a, wp0, u0); u1 = fmaf(a, wp1, u1); u2 = fmaf(a, wp2, u2);
        au = fmaf(a, bp[h], au);
        v0 = fmaf(c, wp0, v0); v1 = fmaf(c, wp1, v1); v2 = fmaf(c, wp2, v2);
        av = fmaf(c, bp[h], av);
        kd = fmaf(wd[h], w2h, kd);
    }
    #pragma unroll
    for (int o = 16; o > 0; o >>= 1) {
        u0 += __shfl_xor_sync(0xFFFFFFFFu, u0, o);
        u1 += __shfl_xor_sync(0xFFFFFFFFu, u1, o);
        u2 += __shfl_xor_sync(0xFFFFFFFFu, u2, o);
        au += __shfl_xor_sync(0xFFFFFFFFu, au, o);
        v0 += __shfl_xor_sync(0xFFFFFFFFu, v0, o);
        v1 += __shfl_xor_sync(0xFFFFFFFFu, v1, o);
        v2 += __shfl_xor_sync(0xFFFFFFFFu, v2, o);
        av += __shfl_xor_sync(0xFFFFFFFFu, av, o);
        kd += __shfl_xor_sync(0xFFFFFFFFu, kd, o);
    }
    if (lane == 0) {
        g_prm[0] = u0 * L2E; g_prm[1] = u1 * L2E; g_prm[2] = u2 * L2E; g_prm[3] = au * L2E;
        g_prm[4] = v0 * L2E; g_prm[5] = v1 * L2E; g_prm[6] = v2 * L2E; g_prm[7] = av * L2E;
        g_prm[8] = kd * L2E;
    }
}

// ---------------------------------------------------------------------------
// Main: one warp per row i, 16 rows/block, all per-batch j-data in SMEM.
// log2-domain score: norm_i*A[j] + C[j] + kd*dist[i,j]*gate
// ---------------------------------------------------------------------------
__global__ __launch_bounds__(THREADS)
void attn_kernel(const float* __restrict__ pos,
                 const void* __restrict__ node_mask,
                 const float* __restrict__ p,
                 const void* __restrict__ pharma,
                 const float* __restrict__ lin1_w,
                 const float* __restrict__ lin1_b,
                 const float* __restrict__ lin2_w,
                 const float* __restrict__ lin2_b,
                 float* __restrict__ out) {
    __shared__ float s_qx[Nn], s_qy[Nn], s_qz[Nn];
    __shared__ float s_px[Nn], s_py[Nn], s_pz[Nn], s_sq[Nn];
    __shared__ float s_A[Nn], s_C[Nn], s_cb[Nn];

    const int b = blockIdx.y;
    const int tid = threadIdx.x;
    const int isB = g_mask_byte;

    const float u0 = g_prm[0], u1 = g_prm[1], u2 = g_prm[2], au = g_prm[3];
    const float v0 = g_prm[4], v1 = g_prm[5], v2 = g_prm[6], av = g_prm[7];
    const float kdL = g_prm[8];

    const float* posb = pos + (size_t)b * Nn * 3;
    const float* pb   = p   + (size_t)b * Nn * 3;

    for (int j = tid; j < Nn; j += THREADS) {
        float qx = posb[j * 3 + 0], qy = posb[j * 3 + 1], qz = posb[j * 3 + 2];
        s_qx[j] = qx; s_qy[j] = qy; s_qz[j] = qz;
        s_A[j] = fmaf(qx, u0, fmaf(qy, u1, fmaf(qz, u2, au)));
        s_C[j] = fmaf(qx, v0, fmaf(qy, v1, fmaf(qz, v2, av)));
        float px = pb[j * 3 + 0], py = pb[j * 3 + 1], pz = pb[j * 3 + 2];
        s_px[j] = px; s_py[j] = py; s_pz[j] = pz;
        s_sq[j] = fmaf(px, px, fmaf(py, py, pz * pz));
        s_cb[j] = mask_at(pharma, b * Nn + j, isB) ? kdL : 0.f;
    }
    __syncthreads();

    const int w = tid >> 5;
    const int lane = tid & 31;
    const int i = blockIdx.x * ROWS_PER_BLOCK + w;
    const int gi = b * Nn + i;

    const float qx = s_qx[i], qy = s_qy[i], qz = s_qz[i];
    const float norm = sqrtf(fmaf(qx, qx, fmaf(qy, qy, qz * qz)));

    // new_norm_i = sum_h relu(norm*l1w + l1b) * l2w  + l2b
    float nn = 0.f;
    #pragma unroll
    for (int h = lane; h < Hh; h += 32) {
        float hid = fmaf(norm, lin1_w[h], lin1_b[h]);
        nn = fmaf(fmaxf(hid, 0.f), lin2_w[h], nn);
    }
    #pragma unroll
    for (int o = 16; o > 0; o >>= 1) nn += __shfl_xor_sync(0xFFFFFFFFu, nn, o);
    nn += lin2_b[0];

    const float pxi = s_px[i], pyi = s_py[i], pzi = s_pz[i], sqi = s_sq[i];
    const bool rowPh = s_cb[i] != 0.f;

    float sum = 0.f, cx = 0.f, cy = 0.f, cz = 0.f;
    if (rowPh) {
        #pragma unroll 4
        for (int j = lane; j < Nn; j += 32) {
            float s = fmaf(norm, s_A[j], s_C[j]);
            float dot = fmaf(pxi, s_px[j], fmaf(pyi, s_py[j], pzi * s_pz[j]));
            float d2 = fmaf(-2.f, dot, sqi + s_sq[j]);
            d2 = fmaxf(d2, 1e-12f);
            float dist = d2 * rsqrtf_(d2);
            float cb = (j == i) ? 0.f : s_cb[j];
            s = fmaf(cb, dist, s);
            float e = ex2f_(s);
            sum += e;
            cx = fmaf(e, s_qx[j], cx);
            cy = fmaf(e, s_qy[j], cy);
            cz = fmaf(e, s_qz[j], cz);
        }
    } else {
        #pragma unroll 4
        for (int j = lane; j < Nn; j += 32) {
            float e = ex2f_(fmaf(norm, s_A[j], s_C[j]));
            sum += e;
            cx = fmaf(e, s_qx[j], cx);
            cy = fmaf(e, s_qy[j], cy);
            cz = fmaf(e, s_qz[j], cz);
        }
    }
    #pragma unroll
    for (int o = 16; o > 0; o >>= 1) {
        sum += __shfl_xor_sync(0xFFFFFFFFu, sum, o);
        cx  += __shfl_xor_sync(0xFFFFFFFFu, cx, o);
        cy  += __shfl_xor_sync(0xFFFFFFFFu, cy, o);
        cz  += __shfl_xor_sync(0xFFFFFFFFu, cz, o);
    }

    if (lane == 0) {
        float f = mask_at(node_mask, gi, isB) ? nn / (sum * (norm + 1e-5f)) : 0.f;
        out[gi * 3 + 0] = qx * cx * f;
        out[gi * 3 + 1] = qy * cy * f;
        out[gi * 3 + 2] = qz * cz * f;
    }
}

// ---------------------------------------------------------------------------
// Per-batch mean subtraction over N (in-place; one block per batch).
// ---------------------------------------------------------------------------
__global__ __launch_bounds__(1024)
void mean_kernel(float* __restrict__ out) {
    const int b = blockIdx.x;
    const int t = threadIdx.x;
    const int gi = (b * Nn + t) * 3;
    float x = out[gi + 0], y = out[gi + 1], z = out[gi + 2];

    float sx = x, sy = y, sz = z;
    #pragma unroll
    for (int o = 16; o > 0; o >>= 1) {
        sx += __shfl_xor_sync(0xFFFFFFFFu, sx, o);
        sy += __shfl_xor_sync(0xFFFFFFFFu, sy, o);
        sz += __shfl_xor_sync(0xFFFFFFFFu, sz, o);
    }
    __shared__ float rx[32], ry[32], rz[32];
    __shared__ float mx, my, mz;
    const int w = t >> 5, lane = t & 31;
    if (lane == 0) { rx[w] = sx; ry[w] = sy; rz[w] = sz; }
    __syncthreads();
    if (w == 0) {
        float ax = rx[lane], ay = ry[lane], az = rz[lane];
        #pragma unroll
        for (int o = 16; o > 0; o >>= 1) {
            ax += __shfl_xor_sync(0xFFFFFFFFu, ax, o);
            ay += __shfl_xor_sync(0xFFFFFFFFu, ay, o);
            az += __shfl_xor_sync(0xFFFFFFFFu, az, o);
        }
        if (lane == 0) {
            mx = ax * (1.f / Nn); my = ay * (1.f / Nn); mz = az * (1.f / Nn);
        }
    }
    __syncthreads();
    out[gi + 0] = x - mx;
    out[gi + 1] = y - my;
    out[gi + 2] = z - mz;
}

extern "C" void kernel_launch(void* const* d_in, const int* in_sizes, int n_in,
                              void* d_out, int out_size) {
    const float* pos       = (const float*)d_in[0];
    const void*  node_mask = d_in[1];
    const float* p         = (const float*)d_in[2];
    const void*  pharma    = d_in[3];
    const float* lin1_w    = (const float*)d_in[4];
    const float* lin1_b    = (const float*)d_in[5];
    const float* lin2_w    = (const float*)d_in[6];
    const float* lin2_b    = (const float*)d_in[7];
    const float* wp        = (const float*)d_in[8];
    const float* bp        = (const float*)d_in[9];
    const float* wd        = (const float*)d_in[10];
    // d_in[11] = bd, d_in[13] = bc: constant softmax shifts -> cancel, unused
    const float* wc        = (const float*)d_in[12];

    detect_kernel<<<1, 1024>>>((const unsigned int*)node_mask);
    setup_kernel<<<1, 32>>>(lin1_w, lin1_b, wp, bp, wd, wc);

    dim3 grid(Nn / ROWS_PER_BLOCK, Bb);
    attn_kernel<<<grid, THREADS>>>(pos, node_mask, p, pharma,
                                   lin1_w, lin1_b, lin2_w, lin2_b,
                                   (float*)d_out);

    mean_kernel<<<Bb, 1024>>>((float*)d_out);
}

// round 3
// speedup vs baseline: 1.2895x; 1.2895x over previous
#include <cuda_runtime.h>

#define Bb 32
#define Nn 1024
#define Hh 128
#define THREADS 256
#define WARPS 8
#define RPT 4                      // rows per warp
#define ROWS_PER_BLOCK (WARPS * RPT)  // 32
#define GRIDX (Nn / ROWS_PER_BLOCK)   // 32

__device__ float g_prm[9];    // u0..2, au, v0..2, av, kd (pre-scaled by log2 e)
__device__ int   g_mask_byte; // 1 = byte bools, 0 = int32
__device__ int   g_cnt[Bb];   // per-batch completion tickets (reset after use)

__device__ __forceinline__ float ex2f_(float x) {
    float y; asm("ex2.approx.ftz.f32 %0, %1;" : "=f"(y) : "f"(x)); return y;
}
__device__ __forceinline__ float rsqrtf_(float x) {
    float y; asm("rsqrt.approx.ftz.f32 %0, %1;" : "=f"(y) : "f"(x)); return y;
}
__device__ __forceinline__ bool mask_at(const void* m, int idx, int isByte) {
    if (isByte) return ((const unsigned char*)m)[idx] != 0;
    return ((const int*)m)[idx] != 0;
}

// ---------------------------------------------------------------------------
// Setup + mask-dtype detection, one launch. 1024 threads scan the mask words;
// warp 0 collapses the H dimension into 9 scalars.
// ---------------------------------------------------------------------------
__global__ __launch_bounds__(1024)
void setup_kernel(const unsigned int* __restrict__ nm,
                  const float* __restrict__ lin1_w,
                  const float* __restrict__ lin1_b,
                  const float* __restrict__ wp,
                  const float* __restrict__ bp,
                  const float* __restrict__ wd,
                  const float* __restrict__ wc) {
    int any = 0;
    for (int k = threadIdx.x; k < (Bb * Nn) / 4; k += 1024)
        if (nm[k] > 1u) any = 1;
    int r = __syncthreads_or(any);
    if (threadIdx.x == 0) g_mask_byte = r ? 1 : 0;

    if (threadIdx.x < 32) {
        const float L2E = 1.4426950408889634f;
        int lane = threadIdx.x;
        float u0 = 0.f, u1 = 0.f, u2 = 0.f, au = 0.f;
        float v0 = 0.f, v1 = 0.f, v2 = 0.f, av = 0.f, kd = 0.f;
        for (int h = lane; h < Hh; h += 32) {
            float w1h = wc[h];
            float w2h = wc[Hh + h];
            float a = lin1_w[h] * w1h;
            float c = lin1_b[h] * w1h;
            float wp0 = wp[h * 3 + 0], wp1 = wp[h * 3 + 1], wp2 = wp[h * 3 + 2];
            u0 = fmaf(a, wp0, u0); u1 = fmaf(a, wp1, u1); u2 = fmaf(a, wp2, u2);
            au = fmaf(a, bp[h], au);
            v0 = fmaf(c, wp0, v0); v1 = fmaf(c, wp1, v1); v2 = fmaf(c, wp2, v2);
            av = fmaf(c, bp[h], av);
            kd = fmaf(wd[h], w2h, kd);
        }
        #pragma unroll
        for (int o = 16; o > 0; o >>= 1) {
            u0 += __shfl_xor_sync(0xFFFFFFFFu, u0, o);
            u1 += __shfl_xor_sync(0xFFFFFFFFu, u1, o);
            u2 += __shfl_xor_sync(0xFFFFFFFFu, u2, o);
            au += __shfl_xor_sync(0xFFFFFFFFu, au, o);
            v0 += __shfl_xor_sync(0xFFFFFFFFu, v0, o);
            v1 += __shfl_xor_sync(0xFFFFFFFFu, v1, o);
            v2 += __shfl_xor_sync(0xFFFFFFFFu, v2, o);
            av += __shfl_xor_sync(0xFFFFFFFFu, av, o);
            kd += __shfl_xor_sync(0xFFFFFFFFu, kd, o);
        }
        if (lane == 0) {
            g_prm[0] = u0 * L2E; g_prm[1] = u1 * L2E; g_prm[2] = u2 * L2E; g_prm[3] = au * L2E;
            g_prm[4] = v0 * L2E; g_prm[5] = v1 * L2E; g_prm[6] = v2 * L2E; g_prm[7] = av * L2E;
            g_prm[8] = kd * L2E;
        }
    }
}

// ---------------------------------------------------------------------------
// Main kernel. Each warp owns 4 rows; lanes strided over j. Packed j-data in
// SMEM: AC=(A,C), P=(-2px,-2py,-2pz,|p|^2), Q=(qx,qy,qz,kd_gate).
// Last block per batch performs the mean subtraction (ticket pattern).
// ---------------------------------------------------------------------------
__global__ __launch_bounds__(THREADS)
void attn_kernel(const float* __restrict__ pos,
                 const void* __restrict__ node_mask,
                 const float* __restrict__ p,
                 const void* __restrict__ pharma,
                 const float* __restrict__ lin1_w,
                 const float* __restrict__ lin1_b,
                 const float* __restrict__ lin2_w,
                 const float* __restrict__ lin2_b,
                 float* __restrict__ out) {
    __shared__ float2 s_AC[Nn];
    __shared__ float4 s_P[Nn];
    __shared__ float4 s_Q[Nn];
    __shared__ float  s_red[WARPS];
    __shared__ float  s_mean[3];
    __shared__ int    s_tk;

    const int b = blockIdx.y;
    const int tid = threadIdx.x;
    const int isB = g_mask_byte;

    const float u0 = g_prm[0], u1 = g_prm[1], u2 = g_prm[2], au = g_prm[3];
    const float v0 = g_prm[4], v1 = g_prm[5], v2 = g_prm[6], av = g_prm[7];
    const float kdL = g_prm[8];

    const float* posb = pos + (size_t)b * Nn * 3;
    const float* pb   = p   + (size_t)b * Nn * 3;

    for (int j = tid; j < Nn; j += THREADS) {
        float qx = posb[j * 3 + 0], qy = posb[j * 3 + 1], qz = posb[j * 3 + 2];
        float A = fmaf(qx, u0, fmaf(qy, u1, fmaf(qz, u2, au)));
        float C = fmaf(qx, v0, fmaf(qy, v1, fmaf(qz, v2, av)));
        s_AC[j] = make_float2(A, C);
        float px = pb[j * 3 + 0], py = pb[j * 3 + 1], pz = pb[j * 3 + 2];
        float sq = fmaf(px, px, fmaf(py, py, pz * pz));
        s_P[j] = make_float4(-2.f * px, -2.f * py, -2.f * pz, sq);
        float cb = mask_at(pharma, b * Nn + j, isB) ? kdL : 0.f;
        s_Q[j] = make_float4(qx, qy, qz, cb);
    }
    __syncthreads();

    const int w = tid >> 5;
    const int lane = tid & 31;
    const int r0 = blockIdx.x * ROWS_PER_BLOCK + w * RPT;

    // per-row state (unrolled -> registers)
    float pxi[RPT], pyi[RPT], pzi[RPT], sqi[RPT], nrm[RPT], rg[RPT];
    int   ir[RPT];
    float sum[RPT], cx[RPT], cy[RPT], cz[RPT];
    #pragma unroll
    for (int r = 0; r < RPT; r++) {
        ir[r] = r0 + r;
        float4 P = s_P[ir[r]];             // warp-broadcast
        pxi[r] = -0.5f * P.x; pyi[r] = -0.5f * P.y; pzi[r] = -0.5f * P.z;
        sqi[r] = P.w;
        float4 Q = s_Q[ir[r]];
        nrm[r] = sqrtf(fmaf(Q.x, Q.x, fmaf(Q.y, Q.y, Q.z * Q.z)));
        rg[r]  = (Q.w != 0.f) ? 1.f : 0.f; // row pharma gate (kdL==0 edge: term vanishes anyway)
        sum[r] = 0.f; cx[r] = 0.f; cy[r] = 0.f; cz[r] = 0.f;
    }

    #pragma unroll 2
    for (int jj = 0; jj < Nn / 32; jj++) {
        const int j = jj * 32 + lane;
        const float2 AC = s_AC[j];
        const float4 P  = s_P[j];
        const float4 Q  = s_Q[j];
        #pragma unroll
        for (int r = 0; r < RPT; r++) {
            float t  = fmaf(P.z, pzi[r], P.w);
            t        = fmaf(P.y, pyi[r], t);
            t        = fmaf(P.x, pxi[r], t);
            float d2 = fmaxf(sqi[r] + t, 1e-12f);
            float dist = d2 * rsqrtf_(d2);
            float cb = (j == ir[r]) ? 0.f : Q.w * rg[r];
            float s  = fmaf(nrm[r], AC.x, AC.y);
            s        = fmaf(cb, dist, s);
            float e  = ex2f_(s);
            sum[r] += e;
            cx[r] = fmaf(e, Q.x, cx[r]);
            cy[r] = fmaf(e, Q.y, cy[r]);
            cz[r] = fmaf(e, Q.z, cz[r]);
        }
    }

    // new_norm per row (warp-cooperative over H)
    float nnv[RPT];
    #pragma unroll
    for (int r = 0; r < RPT; r++) {
        float nn = 0.f;
        #pragma unroll
        for (int h = lane; h < Hh; h += 32) {
            float hid = fmaf(nrm[r], lin1_w[h], lin1_b[h]);
            nn = fmaf(fmaxf(hid, 0.f), lin2_w[h], nn);
        }
        nnv[r] = nn;
    }

    #pragma unroll
    for (int r = 0; r < RPT; r++) {
        #pragma unroll
        for (int o = 16; o > 0; o >>= 1) {
            sum[r] += __shfl_xor_sync(0xFFFFFFFFu, sum[r], o);
            cx[r]  += __shfl_xor_sync(0xFFFFFFFFu, cx[r], o);
            cy[r]  += __shfl_xor_sync(0xFFFFFFFFu, cy[r], o);
            cz[r]  += __shfl_xor_sync(0xFFFFFFFFu, cz[r], o);
            nnv[r] += __shfl_xor_sync(0xFFFFFFFFu, nnv[r], o);
        }
    }

    const float l2b = lin2_b[0];
    #pragma unroll
    for (int r = 0; r < RPT; r++) {
        if (lane == r) {
            int gi = b * Nn + ir[r];
            float4 Q = s_Q[ir[r]];
            float f = mask_at(node_mask, gi, isB)
                        ? (nnv[r] + l2b) / (sum[r] * (nrm[r] + 1e-5f)) : 0.f;
            out[gi * 3 + 0] = Q.x * cx[r] * f;
            out[gi * 3 + 1] = Q.y * cy[r] * f;
            out[gi * 3 + 2] = Q.z * cz[r] * f;
        }
    }

    // ---- fused per-batch mean subtraction: last block of this batch does it
    __threadfence();
    __syncthreads();
    if (tid == 0) s_tk = atomicAdd(&g_cnt[b], 1);
    __syncthreads();
    if (s_tk == GRIDX - 1) {
        __threadfence();
        float ax = 0.f, ay = 0.f, az = 0.f;
        for (int n = tid; n < Nn; n += THREADS) {
            const float* o = out + ((size_t)b * Nn + n) * 3;
            ax += o[0]; ay += o[1]; az += o[2];
        }
        // deterministic block reduction, one component at a time
        float* comps[3] = {&ax, &ay, &az};
        #pragma unroll
        for (int c = 0; c < 3; c++) {
            float v = *comps[c];
            #pragma unroll
            for (int o = 16; o > 0; o >>= 1) v += __shfl_xor_sync(0xFFFFFFFFu, v, o);
            if (lane == 0) s_red[w] = v;
            __syncthreads();
            if (tid == 0) {
                float t = 0.f;
                #pragma unroll
                for (int k = 0; k < WARPS; k++) t += s_red[k];
                s_mean[c] = t * (1.f / Nn);
            }
            __syncthreads();
        }
        float mx = s_mean[0], my = s_mean[1], mz = s_mean[2];
        for (int n = tid; n < Nn; n += THREADS) {
            float* o = out + ((size_t)b * Nn + n) * 3;
            o[0] -= mx; o[1] -= my; o[2] -= mz;
        }
        if (tid == 0) atomicExch(&g_cnt[b], 0);  // reset for next replay
    }
}

extern "C" void kernel_launch(void* const* d_in, const int* in_sizes, int n_in,
                              void* d_out, int out_size) {
    const float* pos       = (const float*)d_in[0];
    const void*  node_mask = d_in[1];
    const float* p         = (const float*)d_in[2];
    const void*  pharma    = d_in[3];
    const float* lin1_w    = (const float*)d_in[4];
    const float* lin1_b    = (const float*)d_in[5];
    const float* lin2_w    = (const float*)d_in[6];
    const float* lin2_b    = (const float*)d_in[7];
    const float* wp        = (const float*)d_in[8];
    const float* bp        = (const float*)d_in[9];
    const float* wd        = (const float*)d_in[10];
    // d_in[11]=bd, d_in[13]=bc: constant softmax shifts -> cancel
    const float* wc        = (const float*)d_in[12];

    setup_kernel<<<1, 1024>>>((const unsigned int*)node_mask,
                              lin1_w, lin1_b, wp, bp, wd, wc);

    dim3 grid(GRIDX, Bb);
    attn_kernel<<<grid, THREADS>>>(pos, node_mask, p, pharma,
                                   lin1_w, lin1_b, lin2_w, lin2_b,
                                   (float*)d_out);
}